// round 1
// baseline (speedup 1.0000x reference)
#include <cuda_runtime.h>
#include <math.h>
#include <stdint.h>

#define STU_NUM 100000
#define PROB_NUM 20000
#define KNOW_NUM 128
#define DIM 128
#define BATCH 8192
#define HIDDEN 512

// Scratch (allocation-free rule: __device__ globals)
__device__ float g_A0[2 * BATCH * DIM];        // [stu*w_stat ; exer*w_kdiff]
__device__ float g_P[2 * BATCH * KNOW_NUM];    // pre-sigmoid logits (stat ; kdiff)
__device__ float g_state[BATCH * KNOW_NUM];
__device__ float g_h1[BATCH * HIDDEN];
__device__ float g_h2[BATCH * (HIDDEN / 2)];
__device__ float g_h3[BATCH * (HIDDEN / 4)];

__device__ __forceinline__ float sigmoidf_(float x) { return 1.0f / (1.0f + expf(-x)); }

// ---------------------------------------------------------------------------
// Kernel 1: gather embeddings and scale by w_stat / w_kdiff.
// Row r < BATCH:      A0[r] = z[student_id[r]] * w_stat
// Row r >= BATCH:     A0[r] = z[exercise_id[r-BATCH]] * w_kdiff
// ---------------------------------------------------------------------------
__global__ void gather_kernel(const float* __restrict__ z,
                              const int* __restrict__ sid,
                              const int* __restrict__ eid,
                              const float* __restrict__ w_stat,
                              const float* __restrict__ w_kdiff,
                              float* __restrict__ A0) {
    const int idx = blockIdx.x * blockDim.x + threadIdx.x;   // float4 index
    const int total = 2 * BATCH * (DIM / 4);
    if (idx >= total) return;
    const int row = idx >> 5;        // DIM/4 = 32 float4 per row
    const int c = idx & 31;
    const float* src;
    const float* w;
    if (row < BATCH) {
        src = z + (size_t)sid[row] * DIM;
        w = w_stat;
    } else {
        src = z + (size_t)eid[row - BATCH] * DIM;
        w = w_kdiff;
    }
    float4 v = reinterpret_cast<const float4*>(src)[c];
    float4 wv = reinterpret_cast<const float4*>(w)[c];
    v.x *= wv.x; v.y *= wv.y; v.z *= wv.z; v.w *= wv.w;
    reinterpret_cast<float4*>(A0)[idx] = v;
}

// ---------------------------------------------------------------------------
// Tiled fp32 GEMM.
// C[M,N] = act( A[M,K] * B + bias )
// BT=false: B is row-major [K,N] (normal NN)
// BT=true : B is row-major [N,K] (C = A * B^T)
// ACT: 0 = none, 1 = tanh
// Block = 256 threads, BK = 8, microtile TM x TN per thread.
// Requires M % BM == 0, N % BN == 0, K % BK == 0 (true for all our shapes).
// ---------------------------------------------------------------------------
template <int BM, int BN, int TM, int TN, bool BT, int ACT>
__global__ __launch_bounds__(256) void gemm_kernel(
    const float* __restrict__ A, const float* __restrict__ B,
    const float* __restrict__ bias, float* __restrict__ C,
    int M, int N, int K) {
    constexpr int BK = 8;
    constexpr int TX = BN / TN;
    constexpr int TY = BM / TM;
    static_assert(TX * TY == 256, "block must be 256 threads");
    static_assert(TM % 4 == 0 && TN % 4 == 0, "");

    __shared__ __align__(16) float As[BK][BM];
    __shared__ __align__(16) float Bs[BK][BN];

    const int tid = threadIdx.x;
    const int tx = tid % TX;
    const int ty = tid / TX;
    const int m0 = blockIdx.y * BM;
    const int n0 = blockIdx.x * BN;

    float acc[TM][TN];
#pragma unroll
    for (int i = 0; i < TM; i++)
#pragma unroll
        for (int j = 0; j < TN; j++) acc[i][j] = 0.0f;

    for (int k0 = 0; k0 < K; k0 += BK) {
        // Load A tile (BM x BK), store transposed into As[k][m]
        {
            constexpr int NV = BM * (BK / 4);
#pragma unroll
            for (int v = tid; v < NV; v += 256) {
                const int m = v / (BK / 4);
                const int c = v % (BK / 4);
                float4 a = *reinterpret_cast<const float4*>(
                    A + (size_t)(m0 + m) * K + k0 + c * 4);
                As[c * 4 + 0][m] = a.x;
                As[c * 4 + 1][m] = a.y;
                As[c * 4 + 2][m] = a.z;
                As[c * 4 + 3][m] = a.w;
            }
        }
        if (!BT) {
            constexpr int NV = BK * (BN / 4);
#pragma unroll
            for (int v = tid; v < NV; v += 256) {
                const int k = v / (BN / 4);
                const int c = v % (BN / 4);
                *reinterpret_cast<float4*>(&Bs[k][c * 4]) =
                    *reinterpret_cast<const float4*>(
                        B + (size_t)(k0 + k) * N + n0 + c * 4);
            }
        } else {
            constexpr int NV = BN * (BK / 4);
#pragma unroll
            for (int v = tid; v < NV; v += 256) {
                const int n = v / (BK / 4);
                const int c = v % (BK / 4);
                float4 b = *reinterpret_cast<const float4*>(
                    B + (size_t)(n0 + n) * K + k0 + c * 4);
                Bs[c * 4 + 0][n] = b.x;
                Bs[c * 4 + 1][n] = b.y;
                Bs[c * 4 + 2][n] = b.z;
                Bs[c * 4 + 3][n] = b.w;
            }
        }
        __syncthreads();

#pragma unroll
        for (int k = 0; k < BK; k++) {
            float a[TM], b[TN];
#pragma unroll
            for (int rc = 0; rc < TM / 4; rc++) {
                float4 av = *reinterpret_cast<const float4*>(
                    &As[k][ty * 4 + rc * (BM / 2)]);
                a[rc * 4 + 0] = av.x; a[rc * 4 + 1] = av.y;
                a[rc * 4 + 2] = av.z; a[rc * 4 + 3] = av.w;
            }
#pragma unroll
            for (int nc = 0; nc < TN / 4; nc++) {
                float4 bv = *reinterpret_cast<const float4*>(
                    &Bs[k][tx * 4 + nc * (BN / 2)]);
                b[nc * 4 + 0] = bv.x; b[nc * 4 + 1] = bv.y;
                b[nc * 4 + 2] = bv.z; b[nc * 4 + 3] = bv.w;
            }
#pragma unroll
            for (int i = 0; i < TM; i++)
#pragma unroll
                for (int j = 0; j < TN; j++)
                    acc[i][j] = fmaf(a[i], b[j], acc[i][j]);
        }
        __syncthreads();
    }

    // Epilogue: bias + activation, float4 stores
#pragma unroll
    for (int rc = 0; rc < TM / 4; rc++) {
#pragma unroll
        for (int i = 0; i < 4; i++) {
            const int m = m0 + ty * 4 + rc * (BM / 2) + i;
#pragma unroll
            for (int nc = 0; nc < TN / 4; nc++) {
                const int n = n0 + tx * 4 + nc * (BN / 2);
                float r[4];
#pragma unroll
                for (int j = 0; j < 4; j++) {
                    float x = acc[rc * 4 + i][nc * 4 + j];
                    if (bias) x += bias[n + j];
                    if (ACT == 1) x = tanhf(x);
                    r[j] = x;
                }
                float4 v;
                v.x = r[0]; v.y = r[1]; v.z = r[2]; v.w = r[3];
                *reinterpret_cast<float4*>(C + (size_t)m * N + n) = v;
            }
        }
    }
}

// ---------------------------------------------------------------------------
// Kernel 3: state = kp * (sigmoid(P_stat + b_stat) - sigmoid(P_kdiff + b_kdiff))
// ---------------------------------------------------------------------------
__global__ void combine_kernel(const float* __restrict__ P,
                               const float* __restrict__ kp,
                               const float* __restrict__ b_stat,
                               const float* __restrict__ b_kdiff,
                               float* __restrict__ state) {
    const int idx = blockIdx.x * blockDim.x + threadIdx.x;   // float4 index
    const int total = BATCH * KNOW_NUM / 4;
    if (idx >= total) return;
    const float bs = b_stat[0];
    const float bk = b_kdiff[0];
    float4 p1 = reinterpret_cast<const float4*>(P)[idx];
    float4 p2 = reinterpret_cast<const float4*>(P + (size_t)BATCH * KNOW_NUM)[idx];
    float4 k4 = reinterpret_cast<const float4*>(kp)[idx];
    float4 o;
    o.x = k4.x * (sigmoidf_(p1.x + bs) - sigmoidf_(p2.x + bk));
    o.y = k4.y * (sigmoidf_(p1.y + bs) - sigmoidf_(p2.y + bk));
    o.z = k4.z * (sigmoidf_(p1.z + bs) - sigmoidf_(p2.z + bk));
    o.w = k4.w * (sigmoidf_(p1.w + bs) - sigmoidf_(p2.w + bk));
    reinterpret_cast<float4*>(state)[idx] = o;
}

// ---------------------------------------------------------------------------
// Final layer: out[b] = sigmoid(dot(h3[b, 0:128], W4) + b4). One warp per row.
// ---------------------------------------------------------------------------
__global__ void final_kernel(const float* __restrict__ h3,
                             const float* __restrict__ W4,
                             const float* __restrict__ b4,
                             float* __restrict__ out) {
    const int warp = (blockIdx.x * blockDim.x + threadIdx.x) >> 5;
    const int lane = threadIdx.x & 31;
    if (warp >= BATCH) return;
    float4 h = reinterpret_cast<const float4*>(h3 + (size_t)warp * 128)[lane];
    float4 w = reinterpret_cast<const float4*>(W4)[lane];
    float s = h.x * w.x + h.y * w.y + h.z * w.z + h.w * w.w;
#pragma unroll
    for (int off = 16; off; off >>= 1) s += __shfl_xor_sync(0xFFFFFFFFu, s, off);
    if (lane == 0) out[warp] = sigmoidf_(s + b4[0]);
}

// ---------------------------------------------------------------------------
// Launch
// ---------------------------------------------------------------------------
extern "C" void kernel_launch(void* const* d_in, const int* in_sizes, int n_in,
                              void* d_out, int out_size) {
    const float* z       = (const float*)d_in[0];
    const int*   sid     = (const int*)d_in[1];
    const int*   eid     = (const int*)d_in[2];
    const float* kp      = (const float*)d_in[3];
    const float* w_stat  = (const float*)d_in[4];
    const float* b_stat  = (const float*)d_in[5];
    const float* w_kdiff = (const float*)d_in[6];
    const float* b_kdiff = (const float*)d_in[7];
    const float* W1      = (const float*)d_in[8];
    const float* b1      = (const float*)d_in[9];
    const float* W2      = (const float*)d_in[10];
    const float* b2      = (const float*)d_in[11];
    const float* W3      = (const float*)d_in[12];
    const float* b3      = (const float*)d_in[13];
    const float* W4      = (const float*)d_in[14];
    const float* b4      = (const float*)d_in[15];
    float* out = (float*)d_out;

    float *pA0, *pP, *pState, *pH1, *pH2, *pH3;
    cudaGetSymbolAddress((void**)&pA0, g_A0);
    cudaGetSymbolAddress((void**)&pP, g_P);
    cudaGetSymbolAddress((void**)&pState, g_state);
    cudaGetSymbolAddress((void**)&pH1, g_h1);
    cudaGetSymbolAddress((void**)&pH2, g_h2);
    cudaGetSymbolAddress((void**)&pH3, g_h3);

    const float* know = z + (size_t)(STU_NUM + PROB_NUM) * DIM;   // [128,128]

    // 1. gather + scale
    {
        int total = 2 * BATCH * (DIM / 4);
        gather_kernel<<<(total + 255) / 256, 256>>>(z, sid, eid, w_stat, w_kdiff, pA0);
    }

    // 2. P = A0 (16384x128) * knowledge^T (128x128, NT)
    gemm_kernel<64, 128, 4, 8, true, 0>
        <<<dim3(KNOW_NUM / 128, (2 * BATCH) / 64), 256>>>(
            pA0, know, nullptr, pP, 2 * BATCH, KNOW_NUM, DIM);

    // 3. state = kp * (sigmoid(stat) - sigmoid(kdiff))
    {
        int total = BATCH * KNOW_NUM / 4;
        combine_kernel<<<(total + 255) / 256, 256>>>(pP, kp, b_stat, b_kdiff, pState);
    }

    // 4. h1 = tanh(state @ W1 + b1)   (8192x128 @ 128x512)
    gemm_kernel<128, 128, 8, 8, false, 1>
        <<<dim3(HIDDEN / 128, BATCH / 128), 256>>>(
            pState, W1, b1, pH1, BATCH, HIDDEN, KNOW_NUM);

    // 5. h2 = tanh(h1 @ W2 + b2)      (8192x512 @ 512x256)
    gemm_kernel<64, 128, 4, 8, false, 1>
        <<<dim3((HIDDEN / 2) / 128, BATCH / 64), 256>>>(
            pH1, W2, b2, pH2, BATCH, HIDDEN / 2, HIDDEN);

    // 6. h3 = tanh(h2 @ W3 + b3)      (8192x256 @ 256x128)
    gemm_kernel<64, 64, 4, 4, false, 1>
        <<<dim3((HIDDEN / 4) / 64, BATCH / 64), 256>>>(
            pH2, W3, b3, pH3, BATCH, HIDDEN / 4, HIDDEN / 2);

    // 7. out = sigmoid(h3 @ W4 + b4)
    final_kernel<<<(BATCH * 32) / 256, 256>>>(pH3, W4, b4, out);
}

// round 3
// speedup vs baseline: 2.2856x; 2.2856x over previous
#include <cuda_runtime.h>
#include <math.h>
#include <stdint.h>

#define STU_NUM 100000
#define PROB_NUM 20000
#define KNOW_NUM 128
#define DIM 128
#define BATCH 8192
#define HIDDEN 512

// ---------------------------------------------------------------------------
// Scratch (__device__ globals; allocation-free rule)
// ---------------------------------------------------------------------------
__device__ float g_A0[2 * BATCH * DIM];          // rounded (z[id] * w)
__device__ float g_P[2 * BATCH * KNOW_NUM];      // logits (stat ; kdiff)
__device__ float g_state[BATCH * KNOW_NUM];      // rounded
__device__ float g_h1[BATCH * HIDDEN];           // rounded
__device__ float g_h2[BATCH * (HIDDEN / 2)];     // rounded
__device__ float g_h3[BATCH * (HIDDEN / 4)];     // fp32 (feeds scalar final)
__device__ float g_knowR[KNOW_NUM * DIM];        // rounded knowledge block
__device__ float g_W1t[HIDDEN * KNOW_NUM];       // [512,128] K-major, rounded
__device__ float g_W2t[(HIDDEN / 2) * HIDDEN];   // [256,512]
__device__ float g_W3t[(HIDDEN / 4) * (HIDDEN / 2)]; // [128,256]

__device__ __forceinline__ float sigmoidf_(float x) { return 1.0f / (1.0f + expf(-x)); }

__device__ __forceinline__ float tf32r(float x) {
    uint32_t u;
    asm("cvt.rna.tf32.f32 %0, %1;" : "=r"(u) : "f"(x));
    return __uint_as_float(u);
}

__device__ __forceinline__ uint32_t smem_u32(const void* p) {
    uint32_t a;
    asm("{ .reg .u64 t; cvta.to.shared.u64 t, %1; cvt.u32.u64 %0, t; }"
        : "=r"(a) : "l"(p));
    return a;
}

#define CP_ASYNC16(dst, src) \
    asm volatile("cp.async.cg.shared.global [%0], [%1], 16;" :: "r"(dst), "l"(src) : "memory")
#define CP_COMMIT() asm volatile("cp.async.commit_group;" ::: "memory")

// m16n8k8 tf32 mma: A row-major, B col-major, fp32 accumulate (in place)
__device__ __forceinline__ void mma_tf32(float* c, const uint32_t a[4],
                                         uint32_t b0, uint32_t b1) {
    asm volatile(
        "mma.sync.aligned.m16n8k8.row.col.f32.tf32.tf32.f32 "
        "{%0,%1,%2,%3}, {%4,%5,%6,%7}, {%8,%9}, {%0,%1,%2,%3};"
        : "+f"(c[0]), "+f"(c[1]), "+f"(c[2]), "+f"(c[3])
        : "r"(a[0]), "r"(a[1]), "r"(a[2]), "r"(a[3]), "r"(b0), "r"(b1));
}

// ---------------------------------------------------------------------------
// Prep: transpose+round W1/W2/W3 to K-major, round knowledge block.
// grid (16,16,4), block (32,8)
// ---------------------------------------------------------------------------
__global__ void prep_kernel(const float* __restrict__ W1, const float* __restrict__ W2,
                            const float* __restrict__ W3, const float* __restrict__ know,
                            float* __restrict__ W1t, float* __restrict__ W2t,
                            float* __restrict__ W3t, float* __restrict__ knowR) {
    __shared__ float t[32][33];
    const int z = blockIdx.z;
    if (z == 3) {
        int idx = (blockIdx.y * gridDim.x + blockIdx.x) * 256 + threadIdx.y * 32 + threadIdx.x;
        if (idx < KNOW_NUM * DIM) knowR[idx] = tf32r(know[idx]);
        return;
    }
    const float* in; float* out; int K, N;
    if (z == 0) { in = W1; out = W1t; K = KNOW_NUM; N = HIDDEN; }
    else if (z == 1) { in = W2; out = W2t; K = HIDDEN; N = HIDDEN / 2; }
    else { in = W3; out = W3t; K = HIDDEN / 2; N = HIDDEN / 4; }
    const int bx = blockIdx.x, by = blockIdx.y;
    if (bx * 32 >= N || by * 32 >= K) return;
    const int x = bx * 32 + threadIdx.x;
#pragma unroll
    for (int i = 0; i < 32; i += 8) {
        int y = by * 32 + threadIdx.y + i;
        t[threadIdx.y + i][threadIdx.x] = in[(size_t)y * N + x];
    }
    __syncthreads();
    const int xo = by * 32 + threadIdx.x;
#pragma unroll
    for (int i = 0; i < 32; i += 8) {
        int yo = bx * 32 + threadIdx.y + i;
        out[(size_t)yo * K + xo] = tf32r(t[threadIdx.x][threadIdx.y + i]);
    }
}

// ---------------------------------------------------------------------------
// Gather: A0[r] = round(z[id] * w)
// ---------------------------------------------------------------------------
__global__ void gather_kernel(const float* __restrict__ z,
                              const int* __restrict__ sid, const int* __restrict__ eid,
                              const float* __restrict__ w_stat, const float* __restrict__ w_kdiff,
                              float* __restrict__ A0) {
    const int idx = blockIdx.x * blockDim.x + threadIdx.x;
    const int total = 2 * BATCH * (DIM / 4);
    if (idx >= total) return;
    const int row = idx >> 5;
    const int c = idx & 31;
    const float* src; const float* w;
    if (row < BATCH) { src = z + (size_t)sid[row] * DIM; w = w_stat; }
    else { src = z + (size_t)eid[row - BATCH] * DIM; w = w_kdiff; }
    float4 v = reinterpret_cast<const float4*>(src)[c];
    float4 wv = reinterpret_cast<const float4*>(w)[c];
    v.x = tf32r(v.x * wv.x); v.y = tf32r(v.y * wv.y);
    v.z = tf32r(v.z * wv.z); v.w = tf32r(v.w * wv.w);
    reinterpret_cast<float4*>(A0)[idx] = v;
}

// ---------------------------------------------------------------------------
// tf32 mma.sync GEMM: C[M,N] = act(A[M,K] @ Bt[N,K]^T + bias)
// CTA tile 128x128, BK=32, 256 threads (8 warps, warp tile 32x64).
// Smem: [row][k] with row stride 36 floats (conflict-free fragment loads).
// 3-stage cp.async pipeline. ACT: 0 none, 1 tanh+round, 2 tanh.
// ---------------------------------------------------------------------------
#define ROWSTRIDE 36
#define STAGE_FLOATS (128 * ROWSTRIDE)               // per operand: 4608
#define STAGE_BYTES  (2 * STAGE_FLOATS * 4)          // A+B: 36864
#define NSTAGES 3
#define GEMM_DYN_SMEM (NSTAGES * STAGE_BYTES)        // 110592

__device__ __forceinline__ void stage_tile(const float* __restrict__ A,
                                           const float* __restrict__ Bt,
                                           int K, int m0, int n0, int k0,
                                           uint32_t sA, uint32_t sB, int tid) {
#pragma unroll
    for (int i = 0; i < 4; i++) {
        int idx = tid + i * 256;
        int r = idx >> 3, c4 = idx & 7;
        uint32_t off = (uint32_t)(r * ROWSTRIDE + c4 * 4) * 4u;
        CP_ASYNC16(sA + off, A + (size_t)(m0 + r) * K + k0 + c4 * 4);
        CP_ASYNC16(sB + off, Bt + (size_t)(n0 + r) * K + k0 + c4 * 4);
    }
    CP_COMMIT();
}

template <int ACT>
__global__ __launch_bounds__(256, 1) void mma_gemm(const float* __restrict__ A,
                                                   const float* __restrict__ Bt,
                                                   const float* __restrict__ bias,
                                                   float* __restrict__ C,
                                                   int M, int N, int K) {
    extern __shared__ __align__(16) char dyn[];
    const uint32_t sbase = smem_u32(dyn);
    const uint32_t* smem_u = reinterpret_cast<const uint32_t*>(dyn);

    const int tid = threadIdx.x;
    const int wid = tid >> 5;
    const int lane = tid & 31;
    const int g = lane >> 2;          // groupID (0..7)
    const int tig = lane & 3;         // thread-in-group (0..3)
    const int wm = (wid & 3) * 32;    // warp M offset in tile
    const int wn = (wid >> 2) * 64;   // warp N offset in tile
    const int m0 = blockIdx.y * 128, n0 = blockIdx.x * 128;
    const int Cn = K >> 5;            // BK=32 chunks

    float acc[2][8][4];
#pragma unroll
    for (int i = 0; i < 2; i++)
#pragma unroll
        for (int j = 0; j < 8; j++)
#pragma unroll
            for (int q = 0; q < 4; q++) acc[i][j][q] = 0.0f;

    stage_tile(A, Bt, K, m0, n0, 0, sbase, sbase + STAGE_FLOATS * 4, tid);
    if (Cn > 1)
        stage_tile(A, Bt, K, m0, n0, 32,
                   sbase + STAGE_BYTES, sbase + STAGE_BYTES + STAGE_FLOATS * 4, tid);

    for (int c = 0; c < Cn; c++) {
        if (c + 1 < Cn) asm volatile("cp.async.wait_group 1;" ::: "memory");
        else            asm volatile("cp.async.wait_group 0;" ::: "memory");
        __syncthreads();

        if (c + 2 < Cn) {
            int buf = (c + 2) % NSTAGES;
            stage_tile(A, Bt, K, m0, n0, (c + 2) * 32,
                       sbase + buf * STAGE_BYTES,
                       sbase + buf * STAGE_BYTES + STAGE_FLOATS * 4, tid);
        }

        const uint32_t* As = smem_u + (c % NSTAGES) * (STAGE_BYTES / 4);
        const uint32_t* Bs = As + STAGE_FLOATS;

#pragma unroll
        for (int kk = 0; kk < 4; kk++) {
            const int kb = kk * 8;
            uint32_t a[2][4];
#pragma unroll
            for (int i = 0; i < 2; i++) {
                const int m = wm + i * 16 + g;
                a[i][0] = As[m * ROWSTRIDE + kb + tig];
                a[i][1] = As[(m + 8) * ROWSTRIDE + kb + tig];
                a[i][2] = As[m * ROWSTRIDE + kb + tig + 4];
                a[i][3] = As[(m + 8) * ROWSTRIDE + kb + tig + 4];
            }
#pragma unroll
            for (int j = 0; j < 8; j++) {
                const int n = wn + j * 8 + g;
                uint32_t b0 = Bs[n * ROWSTRIDE + kb + tig];
                uint32_t b1 = Bs[n * ROWSTRIDE + kb + tig + 4];
                mma_tf32(acc[0][j], a[0], b0, b1);
                mma_tf32(acc[1][j], a[1], b0, b1);
            }
        }
    }

    // Epilogue: bias + activation, float2 stores
#pragma unroll
    for (int i = 0; i < 2; i++) {
        const int row0 = m0 + wm + i * 16 + g;
#pragma unroll
        for (int j = 0; j < 8; j++) {
            const int col = n0 + wn + j * 8 + tig * 2;
            float bx0 = 0.0f, bx1 = 0.0f;
            if (bias) { bx0 = bias[col]; bx1 = bias[col + 1]; }
            float x0 = acc[i][j][0] + bx0;
            float x1 = acc[i][j][1] + bx1;
            float x2 = acc[i][j][2] + bx0;
            float x3 = acc[i][j][3] + bx1;
            if (ACT >= 1) { x0 = tanhf(x0); x1 = tanhf(x1); x2 = tanhf(x2); x3 = tanhf(x3); }
            if (ACT == 1) { x0 = tf32r(x0); x1 = tf32r(x1); x2 = tf32r(x2); x3 = tf32r(x3); }
            float2 lo; lo.x = x0; lo.y = x1;
            float2 hi; hi.x = x2; hi.y = x3;
            *reinterpret_cast<float2*>(C + (size_t)row0 * N + col) = lo;
            *reinterpret_cast<float2*>(C + (size_t)(row0 + 8) * N + col) = hi;
        }
    }
}

// ---------------------------------------------------------------------------
// Combine: state = round(kp * (sigmoid(P_stat + b_stat) - sigmoid(P_kdiff + b_kdiff)))
// ---------------------------------------------------------------------------
__global__ void combine_kernel(const float* __restrict__ P, const float* __restrict__ kp,
                               const float* __restrict__ b_stat, const float* __restrict__ b_kdiff,
                               float* __restrict__ state) {
    const int idx = blockIdx.x * blockDim.x + threadIdx.x;
    const int total = BATCH * KNOW_NUM / 4;
    if (idx >= total) return;
    const float bs = b_stat[0], bk = b_kdiff[0];
    float4 p1 = reinterpret_cast<const float4*>(P)[idx];
    float4 p2 = reinterpret_cast<const float4*>(P + (size_t)BATCH * KNOW_NUM)[idx];
    float4 k4 = reinterpret_cast<const float4*>(kp)[idx];
    float4 o;
    o.x = tf32r(k4.x * (sigmoidf_(p1.x + bs) - sigmoidf_(p2.x + bk)));
    o.y = tf32r(k4.y * (sigmoidf_(p1.y + bs) - sigmoidf_(p2.y + bk)));
    o.z = tf32r(k4.z * (sigmoidf_(p1.z + bs) - sigmoidf_(p2.z + bk)));
    o.w = tf32r(k4.w * (sigmoidf_(p1.w + bs) - sigmoidf_(p2.w + bk)));
    reinterpret_cast<float4*>(state)[idx] = o;
}

// ---------------------------------------------------------------------------
// Final: out[b] = sigmoid(dot(h3[b], W4) + b4). One warp per row.
// ---------------------------------------------------------------------------
__global__ void final_kernel(const float* __restrict__ h3, const float* __restrict__ W4,
                             const float* __restrict__ b4, float* __restrict__ out) {
    const int warp = (blockIdx.x * blockDim.x + threadIdx.x) >> 5;
    const int lane = threadIdx.x & 31;
    if (warp >= BATCH) return;
    float4 h = reinterpret_cast<const float4*>(h3 + (size_t)warp * 128)[lane];
    float4 w = reinterpret_cast<const float4*>(W4)[lane];
    float s = h.x * w.x + h.y * w.y + h.z * w.z + h.w * w.w;
#pragma unroll
    for (int off = 16; off; off >>= 1) s += __shfl_xor_sync(0xFFFFFFFFu, s, off);
    if (lane == 0) out[warp] = sigmoidf_(s + b4[0]);
}

// ---------------------------------------------------------------------------
// Launch
// ---------------------------------------------------------------------------
extern "C" void kernel_launch(void* const* d_in, const int* in_sizes, int n_in,
                              void* d_out, int out_size) {
    const float* z       = (const float*)d_in[0];
    const int*   sid     = (const int*)d_in[1];
    const int*   eid     = (const int*)d_in[2];
    const float* kp      = (const float*)d_in[3];
    const float* w_stat  = (const float*)d_in[4];
    const float* b_stat  = (const float*)d_in[5];
    const float* w_kdiff = (const float*)d_in[6];
    const float* b_kdiff = (const float*)d_in[7];
    const float* W1      = (const float*)d_in[8];
    const float* b1      = (const float*)d_in[9];
    const float* W2      = (const float*)d_in[10];
    const float* b2      = (const float*)d_in[11];
    const float* W3      = (const float*)d_in[12];
    const float* b3      = (const float*)d_in[13];
    const float* W4      = (const float*)d_in[14];
    const float* b4      = (const float*)d_in[15];
    float* out = (float*)d_out;

    float *pA0, *pP, *pState, *pH1, *pH2, *pH3, *pKnowR, *pW1t, *pW2t, *pW3t;
    cudaGetSymbolAddress((void**)&pA0, g_A0);
    cudaGetSymbolAddress((void**)&pP, g_P);
    cudaGetSymbolAddress((void**)&pState, g_state);
    cudaGetSymbolAddress((void**)&pH1, g_h1);
    cudaGetSymbolAddress((void**)&pH2, g_h2);
    cudaGetSymbolAddress((void**)&pH3, g_h3);
    cudaGetSymbolAddress((void**)&pKnowR, g_knowR);
    cudaGetSymbolAddress((void**)&pW1t, g_W1t);
    cudaGetSymbolAddress((void**)&pW2t, g_W2t);
    cudaGetSymbolAddress((void**)&pW3t, g_W3t);

    const float* know = z + (size_t)(STU_NUM + PROB_NUM) * DIM;

    static bool attr_set = false;
    if (!attr_set) {
        cudaFuncSetAttribute(mma_gemm<0>, cudaFuncAttributeMaxDynamicSharedMemorySize, GEMM_DYN_SMEM);
        cudaFuncSetAttribute(mma_gemm<1>, cudaFuncAttributeMaxDynamicSharedMemorySize, GEMM_DYN_SMEM);
        cudaFuncSetAttribute(mma_gemm<2>, cudaFuncAttributeMaxDynamicSharedMemorySize, GEMM_DYN_SMEM);
        attr_set = true;
    }

    // 1. prep: transpose+round weights, round knowledge
    prep_kernel<<<dim3(16, 16, 4), dim3(32, 8)>>>(W1, W2, W3, know, pW1t, pW2t, pW3t, pKnowR);

    // 2. gather + scale + round
    gather_kernel<<<(2 * BATCH * (DIM / 4) + 255) / 256, 256>>>(z, sid, eid, w_stat, w_kdiff, pA0);

    // 3. P = A0 @ knowR^T  (16384 x 128 x 128)
    mma_gemm<0><<<dim3(1, 128), 256, GEMM_DYN_SMEM>>>(pA0, pKnowR, nullptr, pP,
                                                      2 * BATCH, KNOW_NUM, DIM);

    // 4. state
    combine_kernel<<<(BATCH * KNOW_NUM / 4 + 255) / 256, 256>>>(pP, kp, b_stat, b_kdiff, pState);

    // 5. h1 = tanh(state @ W1 + b1)   (8192 x 512 x 128)
    mma_gemm<1><<<dim3(4, 64), 256, GEMM_DYN_SMEM>>>(pState, pW1t, b1, pH1,
                                                     BATCH, HIDDEN, KNOW_NUM);

    // 6. h2 = tanh(h1 @ W2 + b2)      (8192 x 256 x 512)
    mma_gemm<1><<<dim3(2, 64), 256, GEMM_DYN_SMEM>>>(pH1, pW2t, b2, pH2,
                                                     BATCH, HIDDEN / 2, HIDDEN);

    // 7. h3 = tanh(h2 @ W3 + b3)      (8192 x 128 x 256)
    mma_gemm<2><<<dim3(1, 64), 256, GEMM_DYN_SMEM>>>(pH2, pW3t, b3, pH3,
                                                     BATCH, HIDDEN / 4, HIDDEN / 2);

    // 8. out
    final_kernel<<<(BATCH * 32) / 256, 256>>>(pH3, W4, b4, out);
}

// round 5
// speedup vs baseline: 2.3636x; 1.0341x over previous
#include <cuda_runtime.h>
#include <math.h>
#include <stdint.h>

#define STU_NUM 100000
#define PROB_NUM 20000
#define KNOW_NUM 128
#define DIM 128
#define BATCH 8192
#define HIDDEN 512

// ---------------------------------------------------------------------------
// Scratch (__device__ globals; allocation-free rule)
// ---------------------------------------------------------------------------
__device__ float g_state[BATCH * KNOW_NUM];      // rounded
__device__ float g_h1[BATCH * HIDDEN];           // rounded
__device__ float g_h2[BATCH * (HIDDEN / 2)];     // rounded
__device__ float g_knowS[KNOW_NUM * DIM];        // round(know * w_stat)
__device__ float g_knowK[KNOW_NUM * DIM];        // round(know * w_kdiff)
__device__ float g_W1t[HIDDEN * KNOW_NUM];       // [512,128] K-major, rounded
__device__ float g_W2t[(HIDDEN / 2) * HIDDEN];   // [256,512]
__device__ float g_W3t[(HIDDEN / 4) * (HIDDEN / 2)]; // [128,256]

__device__ __forceinline__ float sigmoidf_(float x) { return 1.0f / (1.0f + expf(-x)); }

__device__ __forceinline__ float tf32r(float x) {
    uint32_t u;
    asm("cvt.rna.tf32.f32 %0, %1;" : "=r"(u) : "f"(x));
    return __uint_as_float(u);
}

__device__ __forceinline__ uint32_t smem_u32(const void* p) {
    uint32_t a;
    asm("{ .reg .u64 t; cvta.to.shared.u64 t, %1; cvt.u32.u64 %0, t; }"
        : "=r"(a) : "l"(p));
    return a;
}

#define CP_ASYNC16(dst, src) \
    asm volatile("cp.async.cg.shared.global [%0], [%1], 16;" :: "r"(dst), "l"(src) : "memory")
#define CP_COMMIT() asm volatile("cp.async.commit_group;" ::: "memory")

// m16n8k8 tf32 mma: A row-major, B col-major, fp32 accumulate (in place)
__device__ __forceinline__ void mma_tf32(float* c, const uint32_t a[4],
                                         uint32_t b0, uint32_t b1) {
    asm volatile(
        "mma.sync.aligned.m16n8k8.row.col.f32.tf32.tf32.f32 "
        "{%0,%1,%2,%3}, {%4,%5,%6,%7}, {%8,%9}, {%0,%1,%2,%3};"
        : "+f"(c[0]), "+f"(c[1]), "+f"(c[2]), "+f"(c[3])
        : "r"(a[0]), "r"(a[1]), "r"(a[2]), "r"(a[3]), "r"(b0), "r"(b1));
}

#define ROWSTRIDE 36

// ---------------------------------------------------------------------------
// Prep: transpose+round W1/W2/W3 to K-major; build scaled knowledge mats.
// grid (16,16,4), block (32,8)
// ---------------------------------------------------------------------------
__global__ void prep_kernel(const float* __restrict__ W1, const float* __restrict__ W2,
                            const float* __restrict__ W3, const float* __restrict__ know,
                            const float* __restrict__ w_stat, const float* __restrict__ w_kdiff,
                            float* __restrict__ W1t, float* __restrict__ W2t,
                            float* __restrict__ W3t, float* __restrict__ knowS,
                            float* __restrict__ knowK) {
    __shared__ float t[32][33];
    const int z = blockIdx.z;
    if (z == 3) {
        int idx = (blockIdx.y * gridDim.x + blockIdx.x) * 256 + threadIdx.y * 32 + threadIdx.x;
        if (idx < KNOW_NUM * DIM) {
            float v = know[idx];
            int d = idx & (DIM - 1);
            knowS[idx] = tf32r(v * w_stat[d]);
            knowK[idx] = tf32r(v * w_kdiff[d]);
        }
        return;
    }
    const float* in; float* out; int K, N;
    if (z == 0) { in = W1; out = W1t; K = KNOW_NUM; N = HIDDEN; }
    else if (z == 1) { in = W2; out = W2t; K = HIDDEN; N = HIDDEN / 2; }
    else { in = W3; out = W3t; K = HIDDEN / 2; N = HIDDEN / 4; }
    const int bx = blockIdx.x, by = blockIdx.y;
    if (bx * 32 >= N || by * 32 >= K) return;
    const int x = bx * 32 + threadIdx.x;
#pragma unroll
    for (int i = 0; i < 32; i += 8) {
        int y = by * 32 + threadIdx.y + i;
        t[threadIdx.y + i][threadIdx.x] = in[(size_t)y * N + x];
    }
    __syncthreads();
    const int xo = by * 32 + threadIdx.x;
#pragma unroll
    for (int i = 0; i < 32; i += 8) {
        int yo = bx * 32 + threadIdx.y + i;
        out[(size_t)yo * K + xo] = tf32r(t[threadIdx.x][threadIdx.y + i]);
    }
}

// ---------------------------------------------------------------------------
// Fused kernel 1: gather + dual GEMM + combine.
// Per CTA (BM=64 batch rows, BN=128=KNOW):
//   Pstat = z[sid rows] @ knowS^T ; Pkdiff = z[eid rows] @ knowK^T
//   state = round(kp * (sig(Pstat + bs) - sig(Pkdiff + bk)))
// 256 threads, 8 warps as 2(m) x 4(n), warp tile 32x32 per matrix.
// Stage chunk (k=32): As(64x32) Ak(64x32) Bs(128x32) Bk(128x32), ROWSTRIDE 36.
// ---------------------------------------------------------------------------
#define F1_AS_OFF 0
#define F1_AK_OFF (64 * ROWSTRIDE)
#define F1_BS_OFF (128 * ROWSTRIDE)
#define F1_BK_OFF (256 * ROWSTRIDE)
#define F1_STAGE_FLOATS (384 * ROWSTRIDE)            // 13824
#define F1_STAGE_BYTES  (F1_STAGE_FLOATS * 4)        // 55296
#define F1_NSTAGES 3
#define F1_DYN_SMEM (F1_NSTAGES * F1_STAGE_BYTES)    // 165888

__device__ __forceinline__ void f1_stage(const float* __restrict__ z,
                                         const int* sidS, const int* eidS,
                                         const float* __restrict__ knowS,
                                         const float* __restrict__ knowK,
                                         int k0, uint32_t sbase, int tid) {
#pragma unroll
    for (int i = 0; i < 12; i++) {
        int idx = tid + i * 256;              // 0..3071
        if (idx < 512) {
            int r = idx >> 3, c4 = idx & 7;
            uint32_t off = (uint32_t)(F1_AS_OFF + r * ROWSTRIDE + c4 * 4) * 4u;
            CP_ASYNC16(sbase + off, z + (size_t)sidS[r] * DIM + k0 + c4 * 4);
        } else if (idx < 1024) {
            int t = idx - 512;
            int r = t >> 3, c4 = t & 7;
            uint32_t off = (uint32_t)(F1_AK_OFF + r * ROWSTRIDE + c4 * 4) * 4u;
            CP_ASYNC16(sbase + off, z + (size_t)eidS[r] * DIM + k0 + c4 * 4);
        } else if (idx < 2048) {
            int t = idx - 1024;
            int r = t >> 3, c4 = t & 7;
            uint32_t off = (uint32_t)(F1_BS_OFF + r * ROWSTRIDE + c4 * 4) * 4u;
            CP_ASYNC16(sbase + off, knowS + (size_t)r * DIM + k0 + c4 * 4);
        } else {
            int t = idx - 2048;
            int r = t >> 3, c4 = t & 7;
            uint32_t off = (uint32_t)(F1_BK_OFF + r * ROWSTRIDE + c4 * 4) * 4u;
            CP_ASYNC16(sbase + off, knowK + (size_t)r * DIM + k0 + c4 * 4);
        }
    }
    CP_COMMIT();
}

__global__ __launch_bounds__(256, 1) void fused1_kernel(
    const float* __restrict__ z, const int* __restrict__ sid, const int* __restrict__ eid,
    const float* __restrict__ knowS, const float* __restrict__ knowK,
    const float* __restrict__ kp, const float* __restrict__ b_stat,
    const float* __restrict__ b_kdiff, float* __restrict__ state) {
    extern __shared__ __align__(16) char dyn[];
    __shared__ int sidS[64], eidS[64];
    const uint32_t sbase = smem_u32(dyn);
    const uint32_t* smem_u = reinterpret_cast<const uint32_t*>(dyn);

    const int tid = threadIdx.x;
    const int m0 = blockIdx.x * 64;
    if (tid < 64) sidS[tid] = sid[m0 + tid];
    else if (tid < 128) eidS[tid - 64] = eid[m0 + tid - 64];
    __syncthreads();

    const int wid = tid >> 5, lane = tid & 31;
    const int g = lane >> 2, tig = lane & 3;
    const int wm = (wid & 1) * 32;        // 2 warps in M
    const int wn = (wid >> 1) * 32;       // 4 warps in N

    float accS[2][4][4], accK[2][4][4];
#pragma unroll
    for (int i = 0; i < 2; i++)
#pragma unroll
        for (int j = 0; j < 4; j++)
#pragma unroll
            for (int q = 0; q < 4; q++) { accS[i][j][q] = 0.0f; accK[i][j][q] = 0.0f; }

    f1_stage(z, sidS, eidS, knowS, knowK, 0, sbase, tid);
    f1_stage(z, sidS, eidS, knowS, knowK, 32, sbase + F1_STAGE_BYTES, tid);

    const int Cn = DIM / 32;   // 4
    for (int c = 0; c < Cn; c++) {
        if (c + 1 < Cn) asm volatile("cp.async.wait_group 1;" ::: "memory");
        else            asm volatile("cp.async.wait_group 0;" ::: "memory");
        __syncthreads();
        if (c + 2 < Cn) {
            int buf = (c + 2) % F1_NSTAGES;
            f1_stage(z, sidS, eidS, knowS, knowK, (c + 2) * 32,
                     sbase + buf * F1_STAGE_BYTES, tid);
        }
        const uint32_t* St = smem_u + (c % F1_NSTAGES) * F1_STAGE_FLOATS;

#pragma unroll
        for (int kk = 0; kk < 4; kk++) {
            const int kb = kk * 8;
            uint32_t aS[2][4], aK[2][4];
#pragma unroll
            for (int i = 0; i < 2; i++) {
                const int m = wm + i * 16 + g;
                aS[i][0] = St[F1_AS_OFF + m * ROWSTRIDE + kb + tig];
                aS[i][1] = St[F1_AS_OFF + (m + 8) * ROWSTRIDE + kb + tig];
                aS[i][2] = St[F1_AS_OFF + m * ROWSTRIDE + kb + tig + 4];
                aS[i][3] = St[F1_AS_OFF + (m + 8) * ROWSTRIDE + kb + tig + 4];
                aK[i][0] = St[F1_AK_OFF + m * ROWSTRIDE + kb + tig];
                aK[i][1] = St[F1_AK_OFF + (m + 8) * ROWSTRIDE + kb + tig];
                aK[i][2] = St[F1_AK_OFF + m * ROWSTRIDE + kb + tig + 4];
                aK[i][3] = St[F1_AK_OFF + (m + 8) * ROWSTRIDE + kb + tig + 4];
            }
#pragma unroll
            for (int j = 0; j < 4; j++) {
                const int n = wn + j * 8 + g;
                uint32_t bS0 = St[F1_BS_OFF + n * ROWSTRIDE + kb + tig];
                uint32_t bS1 = St[F1_BS_OFF + n * ROWSTRIDE + kb + tig + 4];
                uint32_t bK0 = St[F1_BK_OFF + n * ROWSTRIDE + kb + tig];
                uint32_t bK1 = St[F1_BK_OFF + n * ROWSTRIDE + kb + tig + 4];
                mma_tf32(accS[0][j], aS[0], bS0, bS1);
                mma_tf32(accS[1][j], aS[1], bS0, bS1);
                mma_tf32(accK[0][j], aK[0], bK0, bK1);
                mma_tf32(accK[1][j], aK[1], bK0, bK1);
            }
        }
    }

    // Epilogue: state = round(kp * (sig(Ps+bs) - sig(Pk+bk)))
    const float bs = b_stat[0], bk = b_kdiff[0];
#pragma unroll
    for (int i = 0; i < 2; i++) {
        const int r0 = m0 + wm + i * 16 + g;
#pragma unroll
        for (int j = 0; j < 4; j++) {
            const int col = wn + j * 8 + tig * 2;
            float2 kpa = *reinterpret_cast<const float2*>(kp + (size_t)r0 * KNOW_NUM + col);
            float2 kpb = *reinterpret_cast<const float2*>(kp + (size_t)(r0 + 8) * KNOW_NUM + col);
            float2 lo, hi;
            lo.x = tf32r(kpa.x * (sigmoidf_(accS[i][j][0] + bs) - sigmoidf_(accK[i][j][0] + bk)));
            lo.y = tf32r(kpa.y * (sigmoidf_(accS[i][j][1] + bs) - sigmoidf_(accK[i][j][1] + bk)));
            hi.x = tf32r(kpb.x * (sigmoidf_(accS[i][j][2] + bs) - sigmoidf_(accK[i][j][2] + bk)));
            hi.y = tf32r(kpb.y * (sigmoidf_(accS[i][j][3] + bs) - sigmoidf_(accK[i][j][3] + bk)));
            *reinterpret_cast<float2*>(state + (size_t)r0 * KNOW_NUM + col) = lo;
            *reinterpret_cast<float2*>(state + (size_t)(r0 + 8) * KNOW_NUM + col) = hi;
        }
    }
}

// ---------------------------------------------------------------------------
// tf32 mma.sync GEMM (h1/h2): C = round(tanh(A @ Bt^T + bias))
// CTA tile 128x128, BK=32, 256 threads (8 warps 4x2, warp tile 32x64).
// ---------------------------------------------------------------------------
#define STAGE_FLOATS (128 * ROWSTRIDE)               // per operand: 4608
#define STAGE_BYTES  (2 * STAGE_FLOATS * 4)          // A+B: 36864
#define NSTAGES 3
#define GEMM_DYN_SMEM (NSTAGES * STAGE_BYTES)        // 110592

__device__ __forceinline__ void stage_tile(const float* __restrict__ A,
                                           const float* __restrict__ Bt,
                                           int K, int m0, int n0, int k0,
                                           uint32_t sA, uint32_t sB, int tid) {
#pragma unroll
    for (int i = 0; i < 4; i++) {
        int idx = tid + i * 256;
        int r = idx >> 3, c4 = idx & 7;
        uint32_t off = (uint32_t)(r * ROWSTRIDE + c4 * 4) * 4u;
        CP_ASYNC16(sA + off, A + (size_t)(m0 + r) * K + k0 + c4 * 4);
        CP_ASYNC16(sB + off, Bt + (size_t)(n0 + r) * K + k0 + c4 * 4);
    }
    CP_COMMIT();
}

__global__ __launch_bounds__(256, 1) void mma_gemm(const float* __restrict__ A,
                                                   const float* __restrict__ Bt,
                                                   const float* __restrict__ bias,
                                                   float* __restrict__ C,
                                                   int M, int N, int K) {
    extern __shared__ __align__(16) char dyn[];
    const uint32_t sbase = smem_u32(dyn);
    const uint32_t* smem_u = reinterpret_cast<const uint32_t*>(dyn);

    const int tid = threadIdx.x;
    const int wid = tid >> 5;
    const int lane = tid & 31;
    const int g = lane >> 2, tig = lane & 3;
    const int wm = (wid & 3) * 32;
    const int wn = (wid >> 2) * 64;
    const int m0 = blockIdx.y * 128, n0 = blockIdx.x * 128;
    const int Cn = K >> 5;

    float acc[2][8][4];
#pragma unroll
    for (int i = 0; i < 2; i++)
#pragma unroll
        for (int j = 0; j < 8; j++)
#pragma unroll
            for (int q = 0; q < 4; q++) acc[i][j][q] = 0.0f;

    stage_tile(A, Bt, K, m0, n0, 0, sbase, sbase + STAGE_FLOATS * 4, tid);
    if (Cn > 1)
        stage_tile(A, Bt, K, m0, n0, 32,
                   sbase + STAGE_BYTES, sbase + STAGE_BYTES + STAGE_FLOATS * 4, tid);

    for (int c = 0; c < Cn; c++) {
        if (c + 1 < Cn) asm volatile("cp.async.wait_group 1;" ::: "memory");
        else            asm volatile("cp.async.wait_group 0;" ::: "memory");
        __syncthreads();
        if (c + 2 < Cn) {
            int buf = (c + 2) % NSTAGES;
            stage_tile(A, Bt, K, m0, n0, (c + 2) * 32,
                       sbase + buf * STAGE_BYTES,
                       sbase + buf * STAGE_BYTES + STAGE_FLOATS * 4, tid);
        }
        const uint32_t* As = smem_u + (c % NSTAGES) * (STAGE_BYTES / 4);
        const uint32_t* Bs = As + STAGE_FLOATS;

#pragma unroll
        for (int kk = 0; kk < 4; kk++) {
            const int kb = kk * 8;
            uint32_t a[2][4];
#pragma unroll
            for (int i = 0; i < 2; i++) {
                const int m = wm + i * 16 + g;
                a[i][0] = As[m * ROWSTRIDE + kb + tig];
                a[i][1] = As[(m + 8) * ROWSTRIDE + kb + tig];
                a[i][2] = As[m * ROWSTRIDE + kb + tig + 4];
                a[i][3] = As[(m + 8) * ROWSTRIDE + kb + tig + 4];
            }
#pragma unroll
            for (int j = 0; j < 8; j++) {
                const int n = wn + j * 8 + g;
                uint32_t b0 = Bs[n * ROWSTRIDE + kb + tig];
                uint32_t b1 = Bs[n * ROWSTRIDE + kb + tig + 4];
                mma_tf32(acc[0][j], a[0], b0, b1);
                mma_tf32(acc[1][j], a[1], b0, b1);
            }
        }
    }

#pragma unroll
    for (int i = 0; i < 2; i++) {
        const int row0 = m0 + wm + i * 16 + g;
#pragma unroll
        for (int j = 0; j < 8; j++) {
            const int col = n0 + wn + j * 8 + tig * 2;
            float bx0 = bias[col], bx1 = bias[col + 1];
            float2 lo, hi;
            lo.x = tf32r(tanhf(acc[i][j][0] + bx0));
            lo.y = tf32r(tanhf(acc[i][j][1] + bx1));
            hi.x = tf32r(tanhf(acc[i][j][2] + bx0));
            hi.y = tf32r(tanhf(acc[i][j][3] + bx1));
            *reinterpret_cast<float2*>(C + (size_t)row0 * N + col) = lo;
            *reinterpret_cast<float2*>(C + (size_t)(row0 + 8) * N + col) = hi;
        }
    }
}

// ---------------------------------------------------------------------------
// Fused kernel D: h3 GEMM (M=8192, N=128, K=256) + final dot/sigmoid.
// out[b] = sigmoid( tanh(h2[b] @ W3t^T + b3) . W4 + b4 )
// ---------------------------------------------------------------------------
#define GD_DYN_SMEM (GEMM_DYN_SMEM + 1024)

__global__ __launch_bounds__(256, 1) void gemm3_final_kernel(
    const float* __restrict__ A, const float* __restrict__ Bt,
    const float* __restrict__ bias, const float* __restrict__ W4,
    const float* __restrict__ b4, float* __restrict__ out) {
    extern __shared__ __align__(16) char dyn[];
    const uint32_t sbase = smem_u32(dyn);
    const uint32_t* smem_u = reinterpret_cast<const uint32_t*>(dyn);
    float* sred = reinterpret_cast<float*>(dyn + GEMM_DYN_SMEM);  // [128][2]

    const int K = HIDDEN / 2;   // 256
    const int tid = threadIdx.x;
    const int wid = tid >> 5;
    const int lane = tid & 31;
    const int g = lane >> 2, tig = lane & 3;
    const int wm = (wid & 3) * 32;
    const int wn = (wid >> 2) * 64;
    const int wnIdx = wid >> 2;
    const int m0 = blockIdx.x * 128;
    const int Cn = K >> 5;   // 8

    float acc[2][8][4];
#pragma unroll
    for (int i = 0; i < 2; i++)
#pragma unroll
        for (int j = 0; j < 8; j++)
#pragma unroll
            for (int q = 0; q < 4; q++) acc[i][j][q] = 0.0f;

    stage_tile(A, Bt, K, m0, 0, 0, sbase, sbase + STAGE_FLOATS * 4, tid);
    stage_tile(A, Bt, K, m0, 0, 32,
               sbase + STAGE_BYTES, sbase + STAGE_BYTES + STAGE_FLOATS * 4, tid);

    for (int c = 0; c < Cn; c++) {
        if (c + 1 < Cn) asm volatile("cp.async.wait_group 1;" ::: "memory");
        else            asm volatile("cp.async.wait_group 0;" ::: "memory");
        __syncthreads();
        if (c + 2 < Cn) {
            int buf = (c + 2) % NSTAGES;
            stage_tile(A, Bt, K, m0, 0, (c + 2) * 32,
                       sbase + buf * STAGE_BYTES,
                       sbase + buf * STAGE_BYTES + STAGE_FLOATS * 4, tid);
        }
        const uint32_t* As = smem_u + (c % NSTAGES) * (STAGE_BYTES / 4);
        const uint32_t* Bs = As + STAGE_FLOATS;

#pragma unroll
        for (int kk = 0; kk < 4; kk++) {
            const int kb = kk * 8;
            uint32_t a[2][4];
#pragma unroll
            for (int i = 0; i < 2; i++) {
                const int m = wm + i * 16 + g;
                a[i][0] = As[m * ROWSTRIDE + kb + tig];
                a[i][1] = As[(m + 8) * ROWSTRIDE + kb + tig];
                a[i][2] = As[m * ROWSTRIDE + kb + tig + 4];
                a[i][3] = As[(m + 8) * ROWSTRIDE + kb + tig + 4];
            }
#pragma unroll
            for (int j = 0; j < 8; j++) {
                const int n = wn + j * 8 + g;
                uint32_t b0 = Bs[n * ROWSTRIDE + kb + tig];
                uint32_t b1 = Bs[n * ROWSTRIDE + kb + tig + 4];
                mma_tf32(acc[0][j], a[0], b0, b1);
                mma_tf32(acc[1][j], a[1], b0, b1);
            }
        }
    }

    // Fused reduction epilogue
    float part[2][2] = {{0.0f, 0.0f}, {0.0f, 0.0f}};
#pragma unroll
    for (int i = 0; i < 2; i++) {
#pragma unroll
        for (int j = 0; j < 8; j++) {
            const int col = wn + j * 8 + tig * 2;
            float w0 = W4[col], w1 = W4[col + 1];
            float bc0 = bias[col], bc1 = bias[col + 1];
            part[i][0] += tanhf(acc[i][j][0] + bc0) * w0 + tanhf(acc[i][j][1] + bc1) * w1;
            part[i][1] += tanhf(acc[i][j][2] + bc0) * w0 + tanhf(acc[i][j][3] + bc1) * w1;
        }
    }
#pragma unroll
    for (int i = 0; i < 2; i++)
#pragma unroll
        for (int h = 0; h < 2; h++) {
            part[i][h] += __shfl_xor_sync(0xFFFFFFFFu, part[i][h], 1);
            part[i][h] += __shfl_xor_sync(0xFFFFFFFFu, part[i][h], 2);
        }
    if (tig == 0) {
#pragma unroll
        for (int i = 0; i < 2; i++)
#pragma unroll
            for (int h = 0; h < 2; h++)
                sred[(wm + i * 16 + g + h * 8) * 2 + wnIdx] = part[i][h];
    }
    __syncthreads();
    if (tid < 128) {
        float s = sred[tid * 2] + sred[tid * 2 + 1] + b4[0];
        out[m0 + tid] = sigmoidf_(s);
    }
}

// ---------------------------------------------------------------------------
// Launch
// ---------------------------------------------------------------------------
extern "C" void kernel_launch(void* const* d_in, const int* in_sizes, int n_in,
                              void* d_out, int out_size) {
    const float* z       = (const float*)d_in[0];
    const int*   sid     = (const int*)d_in[1];
    const int*   eid     = (const int*)d_in[2];
    const float* kp      = (const float*)d_in[3];
    const float* w_stat  = (const float*)d_in[4];
    const float* b_stat  = (const float*)d_in[5];
    const float* w_kdiff = (const float*)d_in[6];
    const float* b_kdiff = (const float*)d_in[7];
    const float* W1      = (const float*)d_in[8];
    const float* b1      = (const float*)d_in[9];
    const float* W2      = (const float*)d_in[10];
    const float* b2      = (const float*)d_in[11];
    const float* W3      = (const float*)d_in[12];
    const float* b3      = (const float*)d_in[13];
    const float* W4      = (const float*)d_in[14];
    const float* b4      = (const float*)d_in[15];
    float* out = (float*)d_out;

    float *pState, *pH1, *pH2, *pKnowS, *pKnowK, *pW1t, *pW2t, *pW3t;
    cudaGetSymbolAddress((void**)&pState, g_state);
    cudaGetSymbolAddress((void**)&pH1, g_h1);
    cudaGetSymbolAddress((void**)&pH2, g_h2);
    cudaGetSymbolAddress((void**)&pKnowS, g_knowS);
    cudaGetSymbolAddress((void**)&pKnowK, g_knowK);
    cudaGetSymbolAddress((void**)&pW1t, g_W1t);
    cudaGetSymbolAddress((void**)&pW2t, g_W2t);
    cudaGetSymbolAddress((void**)&pW3t, g_W3t);

    const float* know = z + (size_t)(STU_NUM + PROB_NUM) * DIM;

    static bool attr_set = false;
    if (!attr_set) {
        cudaFuncSetAttribute(fused1_kernel, cudaFuncAttributeMaxDynamicSharedMemorySize, F1_DYN_SMEM);
        cudaFuncSetAttribute(mma_gemm, cudaFuncAttributeMaxDynamicSharedMemorySize, GEMM_DYN_SMEM);
        cudaFuncSetAttribute(gemm3_final_kernel, cudaFuncAttributeMaxDynamicSharedMemorySize, GD_DYN_SMEM);
        attr_set = true;
    }

    // 1. prep
    prep_kernel<<<dim3(16, 16, 4), dim3(32, 8)>>>(W1, W2, W3, know, w_stat, w_kdiff,
                                                  pW1t, pW2t, pW3t, pKnowS, pKnowK);

    // 2. fused gather + dual GEMM + combine -> state
    fused1_kernel<<<BATCH / 64, 256, F1_DYN_SMEM>>>(z, sid, eid, pKnowS, pKnowK,
                                                    kp, b_stat, b_kdiff, pState);

    // 3. h1 = round(tanh(state @ W1 + b1))   (8192 x 512 x 128)
    mma_gemm<<<dim3(4, 64), 256, GEMM_DYN_SMEM>>>(pState, pW1t, b1, pH1,
                                                  BATCH, HIDDEN, KNOW_NUM);

    // 4. h2 = round(tanh(h1 @ W2 + b2))      (8192 x 256 x 512)
    mma_gemm<<<dim3(2, 64), 256, GEMM_DYN_SMEM>>>(pH1, pW2t, b2, pH2,
                                                  BATCH, HIDDEN / 2, HIDDEN);

    // 5. fused h3 GEMM + final dot + sigmoid
    gemm3_final_kernel<<<BATCH / 128, 256, GD_DYN_SMEM>>>(pH2, pW3t, b3, W4, b4, out);
}

// round 6
// speedup vs baseline: 2.4949x; 1.0555x over previous
#include <cuda_runtime.h>
#include <math.h>
#include <stdint.h>

#define STU_NUM 100000
#define PROB_NUM 20000
#define KNOW_NUM 128
#define DIM 128
#define BATCH 8192
#define HIDDEN 512

// ---------------------------------------------------------------------------
// Scratch (__device__ globals; allocation-free rule)
// ---------------------------------------------------------------------------
__device__ float g_state[BATCH * KNOW_NUM];      // rounded
__device__ float g_h1[BATCH * HIDDEN];           // rounded
__device__ float g_h2[BATCH * (HIDDEN / 2)];     // rounded
__device__ float g_knowS[KNOW_NUM * DIM];        // round(know * w_stat)
__device__ float g_knowK[KNOW_NUM * DIM];        // round(know * w_kdiff)
__device__ float g_W1t[HIDDEN * KNOW_NUM];       // [512,128] K-major, rounded
__device__ float g_W2t[(HIDDEN / 2) * HIDDEN];   // [256,512]
__device__ float g_W3t[(HIDDEN / 4) * (HIDDEN / 2)]; // [128,256]

__device__ __forceinline__ float sigmoidf_(float x) { return 1.0f / (1.0f + expf(-x)); }

__device__ __forceinline__ float tf32r(float x) {
    uint32_t u;
    asm("cvt.rna.tf32.f32 %0, %1;" : "=r"(u) : "f"(x));
    return __uint_as_float(u);
}

__device__ __forceinline__ uint32_t smem_u32(const void* p) {
    uint32_t a;
    asm("{ .reg .u64 t; cvta.to.shared.u64 t, %1; cvt.u32.u64 %0, t; }"
        : "=r"(a) : "l"(p));
    return a;
}

#define CP_ASYNC16(dst, src) \
    asm volatile("cp.async.cg.shared.global [%0], [%1], 16;" :: "r"(dst), "l"(src) : "memory")
#define CP_COMMIT() asm volatile("cp.async.commit_group;" ::: "memory")

// m16n8k8 tf32 mma: A row-major, B col-major, fp32 accumulate (in place)
__device__ __forceinline__ void mma_tf32(float* c, const uint32_t a[4],
                                         uint32_t b0, uint32_t b1) {
    asm volatile(
        "mma.sync.aligned.m16n8k8.row.col.f32.tf32.tf32.f32 "
        "{%0,%1,%2,%3}, {%4,%5,%6,%7}, {%8,%9}, {%0,%1,%2,%3};"
        : "+f"(c[0]), "+f"(c[1]), "+f"(c[2]), "+f"(c[3])
        : "r"(a[0]), "r"(a[1]), "r"(a[2]), "r"(a[3]), "r"(b0), "r"(b1));
}

#define ROWSTRIDE 36

// ---------------------------------------------------------------------------
// Prep: transpose+round W1/W2/W3 to K-major; build scaled knowledge mats.
// grid (16,16,4), block (32,8)
// ---------------------------------------------------------------------------
__global__ void prep_kernel(const float* __restrict__ W1, const float* __restrict__ W2,
                            const float* __restrict__ W3, const float* __restrict__ know,
                            const float* __restrict__ w_stat, const float* __restrict__ w_kdiff,
                            float* __restrict__ W1t, float* __restrict__ W2t,
                            float* __restrict__ W3t, float* __restrict__ knowS,
                            float* __restrict__ knowK) {
    __shared__ float t[32][33];
    const int z = blockIdx.z;
    if (z == 3) {
        int idx = (blockIdx.y * gridDim.x + blockIdx.x) * 256 + threadIdx.y * 32 + threadIdx.x;
        if (idx < KNOW_NUM * DIM) {
            float v = know[idx];
            int d = idx & (DIM - 1);
            knowS[idx] = tf32r(v * w_stat[d]);
            knowK[idx] = tf32r(v * w_kdiff[d]);
        }
        return;
    }
    const float* in; float* out; int K, N;
    if (z == 0) { in = W1; out = W1t; K = KNOW_NUM; N = HIDDEN; }
    else if (z == 1) { in = W2; out = W2t; K = HIDDEN; N = HIDDEN / 2; }
    else { in = W3; out = W3t; K = HIDDEN / 2; N = HIDDEN / 4; }
    const int bx = blockIdx.x, by = blockIdx.y;
    if (bx * 32 >= N || by * 32 >= K) return;
    const int x = bx * 32 + threadIdx.x;
#pragma unroll
    for (int i = 0; i < 32; i += 8) {
        int y = by * 32 + threadIdx.y + i;
        t[threadIdx.y + i][threadIdx.x] = in[(size_t)y * N + x];
    }
    __syncthreads();
    const int xo = by * 32 + threadIdx.x;
#pragma unroll
    for (int i = 0; i < 32; i += 8) {
        int yo = bx * 32 + threadIdx.y + i;
        out[(size_t)yo * K + xo] = tf32r(t[threadIdx.x][threadIdx.y + i]);
    }
}

// ---------------------------------------------------------------------------
// Fused kernel 1: gather + dual GEMM + combine (unchanged from R5).
// ---------------------------------------------------------------------------
#define F1_AS_OFF 0
#define F1_AK_OFF (64 * ROWSTRIDE)
#define F1_BS_OFF (128 * ROWSTRIDE)
#define F1_BK_OFF (256 * ROWSTRIDE)
#define F1_STAGE_FLOATS (384 * ROWSTRIDE)            // 13824
#define F1_STAGE_BYTES  (F1_STAGE_FLOATS * 4)        // 55296
#define F1_NSTAGES 3
#define F1_DYN_SMEM (F1_NSTAGES * F1_STAGE_BYTES)    // 165888

__device__ __forceinline__ void f1_stage(const float* __restrict__ z,
                                         const int* sidS, const int* eidS,
                                         const float* __restrict__ knowS,
                                         const float* __restrict__ knowK,
                                         int k0, uint32_t sbase, int tid) {
#pragma unroll
    for (int i = 0; i < 12; i++) {
        int idx = tid + i * 256;              // 0..3071
        if (idx < 512) {
            int r = idx >> 3, c4 = idx & 7;
            uint32_t off = (uint32_t)(F1_AS_OFF + r * ROWSTRIDE + c4 * 4) * 4u;
            CP_ASYNC16(sbase + off, z + (size_t)sidS[r] * DIM + k0 + c4 * 4);
        } else if (idx < 1024) {
            int t = idx - 512;
            int r = t >> 3, c4 = t & 7;
            uint32_t off = (uint32_t)(F1_AK_OFF + r * ROWSTRIDE + c4 * 4) * 4u;
            CP_ASYNC16(sbase + off, z + (size_t)eidS[r] * DIM + k0 + c4 * 4);
        } else if (idx < 2048) {
            int t = idx - 1024;
            int r = t >> 3, c4 = t & 7;
            uint32_t off = (uint32_t)(F1_BS_OFF + r * ROWSTRIDE + c4 * 4) * 4u;
            CP_ASYNC16(sbase + off, knowS + (size_t)r * DIM + k0 + c4 * 4);
        } else {
            int t = idx - 2048;
            int r = t >> 3, c4 = t & 7;
            uint32_t off = (uint32_t)(F1_BK_OFF + r * ROWSTRIDE + c4 * 4) * 4u;
            CP_ASYNC16(sbase + off, knowK + (size_t)r * DIM + k0 + c4 * 4);
        }
    }
    CP_COMMIT();
}

__global__ __launch_bounds__(256, 1) void fused1_kernel(
    const float* __restrict__ z, const int* __restrict__ sid, const int* __restrict__ eid,
    const float* __restrict__ knowS, const float* __restrict__ knowK,
    const float* __restrict__ kp, const float* __restrict__ b_stat,
    const float* __restrict__ b_kdiff, float* __restrict__ state) {
    extern __shared__ __align__(16) char dyn[];
    __shared__ int sidS[64], eidS[64];
    const uint32_t sbase = smem_u32(dyn);
    const uint32_t* smem_u = reinterpret_cast<const uint32_t*>(dyn);

    const int tid = threadIdx.x;
    const int m0 = blockIdx.x * 64;
    if (tid < 64) sidS[tid] = sid[m0 + tid];
    else if (tid < 128) eidS[tid - 64] = eid[m0 + tid - 64];
    __syncthreads();

    const int wid = tid >> 5, lane = tid & 31;
    const int g = lane >> 2, tig = lane & 3;
    const int wm = (wid & 1) * 32;        // 2 warps in M
    const int wn = (wid >> 1) * 32;       // 4 warps in N

    float accS[2][4][4], accK[2][4][4];
#pragma unroll
    for (int i = 0; i < 2; i++)
#pragma unroll
        for (int j = 0; j < 4; j++)
#pragma unroll
            for (int q = 0; q < 4; q++) { accS[i][j][q] = 0.0f; accK[i][j][q] = 0.0f; }

    f1_stage(z, sidS, eidS, knowS, knowK, 0, sbase, tid);
    f1_stage(z, sidS, eidS, knowS, knowK, 32, sbase + F1_STAGE_BYTES, tid);

    const int Cn = DIM / 32;   // 4
    for (int c = 0; c < Cn; c++) {
        if (c + 1 < Cn) asm volatile("cp.async.wait_group 1;" ::: "memory");
        else            asm volatile("cp.async.wait_group 0;" ::: "memory");
        __syncthreads();
        if (c + 2 < Cn) {
            int buf = (c + 2) % F1_NSTAGES;
            f1_stage(z, sidS, eidS, knowS, knowK, (c + 2) * 32,
                     sbase + buf * F1_STAGE_BYTES, tid);
        }
        const uint32_t* St = smem_u + (c % F1_NSTAGES) * F1_STAGE_FLOATS;

#pragma unroll
        for (int kk = 0; kk < 4; kk++) {
            const int kb = kk * 8;
            uint32_t aS[2][4], aK[2][4];
#pragma unroll
            for (int i = 0; i < 2; i++) {
                const int m = wm + i * 16 + g;
                aS[i][0] = St[F1_AS_OFF + m * ROWSTRIDE + kb + tig];
                aS[i][1] = St[F1_AS_OFF + (m + 8) * ROWSTRIDE + kb + tig];
                aS[i][2] = St[F1_AS_OFF + m * ROWSTRIDE + kb + tig + 4];
                aS[i][3] = St[F1_AS_OFF + (m + 8) * ROWSTRIDE + kb + tig + 4];
                aK[i][0] = St[F1_AK_OFF + m * ROWSTRIDE + kb + tig];
                aK[i][1] = St[F1_AK_OFF + (m + 8) * ROWSTRIDE + kb + tig];
                aK[i][2] = St[F1_AK_OFF + m * ROWSTRIDE + kb + tig + 4];
                aK[i][3] = St[F1_AK_OFF + (m + 8) * ROWSTRIDE + kb + tig + 4];
            }
#pragma unroll
            for (int j = 0; j < 4; j++) {
                const int n = wn + j * 8 + g;
                uint32_t bS0 = St[F1_BS_OFF + n * ROWSTRIDE + kb + tig];
                uint32_t bS1 = St[F1_BS_OFF + n * ROWSTRIDE + kb + tig + 4];
                uint32_t bK0 = St[F1_BK_OFF + n * ROWSTRIDE + kb + tig];
                uint32_t bK1 = St[F1_BK_OFF + n * ROWSTRIDE + kb + tig + 4];
                mma_tf32(accS[0][j], aS[0], bS0, bS1);
                mma_tf32(accS[1][j], aS[1], bS0, bS1);
                mma_tf32(accK[0][j], aK[0], bK0, bK1);
                mma_tf32(accK[1][j], aK[1], bK0, bK1);
            }
        }
    }

    // Epilogue: state = round(kp * (sig(Ps+bs) - sig(Pk+bk)))
    const float bs = b_stat[0], bk = b_kdiff[0];
#pragma unroll
    for (int i = 0; i < 2; i++) {
        const int r0 = m0 + wm + i * 16 + g;
#pragma unroll
        for (int j = 0; j < 4; j++) {
            const int col = wn + j * 8 + tig * 2;
            float2 kpa = *reinterpret_cast<const float2*>(kp + (size_t)r0 * KNOW_NUM + col);
            float2 kpb = *reinterpret_cast<const float2*>(kp + (size_t)(r0 + 8) * KNOW_NUM + col);
            float2 lo, hi;
            lo.x = tf32r(kpa.x * (sigmoidf_(accS[i][j][0] + bs) - sigmoidf_(accK[i][j][0] + bk)));
            lo.y = tf32r(kpa.y * (sigmoidf_(accS[i][j][1] + bs) - sigmoidf_(accK[i][j][1] + bk)));
            hi.x = tf32r(kpb.x * (sigmoidf_(accS[i][j][2] + bs) - sigmoidf_(accK[i][j][2] + bk)));
            hi.y = tf32r(kpb.y * (sigmoidf_(accS[i][j][3] + bs) - sigmoidf_(accK[i][j][3] + bk)));
            *reinterpret_cast<float2*>(state + (size_t)r0 * KNOW_NUM + col) = lo;
            *reinterpret_cast<float2*>(state + (size_t)(r0 + 8) * KNOW_NUM + col) = hi;
        }
    }
}

// ---------------------------------------------------------------------------
// Occupancy-tuned tf32 GEMM: CTA tile 64x128, 128 threads (4 warps 2m x 2n,
// warp tile 32x64), BK=32, 2-stage cp.async. 55KB smem -> 3 CTAs/SM.
// C = round(tanh(A[M,K] @ Bt[N,K]^T + bias))
// ---------------------------------------------------------------------------
#define G64_STAGE_FLOATS ((64 + 128) * ROWSTRIDE)    // 6912
#define G64_STAGE_BYTES  (G64_STAGE_FLOATS * 4)      // 27648
#define G64_DYN_SMEM     (2 * G64_STAGE_BYTES)       // 55296

__device__ __forceinline__ void g64_stage(const float* __restrict__ A,
                                          const float* __restrict__ Bt,
                                          int K, int m0, int n0, int k0,
                                          uint32_t sbase, int tid) {
    const uint32_t sB = sbase + 64 * ROWSTRIDE * 4;
#pragma unroll
    for (int i = 0; i < 12; i++) {
        int idx = tid + i * 128;              // 0..1535
        if (idx < 512) {
            int r = idx >> 3, c4 = idx & 7;
            uint32_t off = (uint32_t)(r * ROWSTRIDE + c4 * 4) * 4u;
            CP_ASYNC16(sbase + off, A + (size_t)(m0 + r) * K + k0 + c4 * 4);
        } else {
            int t = idx - 512;
            int r = t >> 3, c4 = t & 7;
            uint32_t off = (uint32_t)(r * ROWSTRIDE + c4 * 4) * 4u;
            CP_ASYNC16(sB + off, Bt + (size_t)(n0 + r) * K + k0 + c4 * 4);
        }
    }
    CP_COMMIT();
}

__global__ __launch_bounds__(128, 3) void mma_gemm64(const float* __restrict__ A,
                                                     const float* __restrict__ Bt,
                                                     const float* __restrict__ bias,
                                                     float* __restrict__ C,
                                                     int M, int N, int K) {
    extern __shared__ __align__(16) char dyn[];
    const uint32_t sbase = smem_u32(dyn);
    const uint32_t* smem_u = reinterpret_cast<const uint32_t*>(dyn);

    const int tid = threadIdx.x;
    const int wid = tid >> 5;
    const int lane = tid & 31;
    const int g = lane >> 2, tig = lane & 3;
    const int wm = (wid & 1) * 32;        // 2 warps in M
    const int wn = (wid >> 1) * 64;       // 2 warps in N
    const int m0 = blockIdx.y * 64, n0 = blockIdx.x * 128;
    const int Cn = K >> 5;

    float acc[2][8][4];
#pragma unroll
    for (int i = 0; i < 2; i++)
#pragma unroll
        for (int j = 0; j < 8; j++)
#pragma unroll
            for (int q = 0; q < 4; q++) acc[i][j][q] = 0.0f;

    g64_stage(A, Bt, K, m0, n0, 0, sbase, tid);

    for (int c = 0; c < Cn; c++) {
        if (c + 1 < Cn) {
            g64_stage(A, Bt, K, m0, n0, (c + 1) * 32,
                      sbase + ((c + 1) & 1) * G64_STAGE_BYTES, tid);
            asm volatile("cp.async.wait_group 1;" ::: "memory");
        } else {
            asm volatile("cp.async.wait_group 0;" ::: "memory");
        }
        __syncthreads();

        const uint32_t* As = smem_u + (c & 1) * G64_STAGE_FLOATS;
        const uint32_t* Bs = As + 64 * ROWSTRIDE;

#pragma unroll
        for (int kk = 0; kk < 4; kk++) {
            const int kb = kk * 8;
            uint32_t a[2][4];
#pragma unroll
            for (int i = 0; i < 2; i++) {
                const int m = wm + i * 16 + g;
                a[i][0] = As[m * ROWSTRIDE + kb + tig];
                a[i][1] = As[(m + 8) * ROWSTRIDE + kb + tig];
                a[i][2] = As[m * ROWSTRIDE + kb + tig + 4];
                a[i][3] = As[(m + 8) * ROWSTRIDE + kb + tig + 4];
            }
#pragma unroll
            for (int j = 0; j < 8; j++) {
                const int n = wn + j * 8 + g;
                uint32_t b0 = Bs[n * ROWSTRIDE + kb + tig];
                uint32_t b1 = Bs[n * ROWSTRIDE + kb + tig + 4];
                mma_tf32(acc[0][j], a[0], b0, b1);
                mma_tf32(acc[1][j], a[1], b0, b1);
            }
        }
        __syncthreads();
    }

#pragma unroll
    for (int i = 0; i < 2; i++) {
        const int row0 = m0 + wm + i * 16 + g;
#pragma unroll
        for (int j = 0; j < 8; j++) {
            const int col = n0 + wn + j * 8 + tig * 2;
            float bx0 = bias[col], bx1 = bias[col + 1];
            float2 lo, hi;
            lo.x = tf32r(tanhf(acc[i][j][0] + bx0));
            lo.y = tf32r(tanhf(acc[i][j][1] + bx1));
            hi.x = tf32r(tanhf(acc[i][j][2] + bx0));
            hi.y = tf32r(tanhf(acc[i][j][3] + bx1));
            *reinterpret_cast<float2*>(C + (size_t)row0 * N + col) = lo;
            *reinterpret_cast<float2*>(C + (size_t)(row0 + 8) * N + col) = hi;
        }
    }
}

// ---------------------------------------------------------------------------
// Fused kernel D: h3 GEMM (tile 64x128, K=256) + final dot/sigmoid.
// out[b] = sigmoid( tanh(h2[b] @ W3t^T + b3) . W4 + b4 )
// 128 threads, grid = BATCH/64 = 128 CTAs.
// ---------------------------------------------------------------------------
#define GD_DYN_SMEM (G64_DYN_SMEM + 512)

__global__ __launch_bounds__(128, 3) void gemm3_final_kernel(
    const float* __restrict__ A, const float* __restrict__ Bt,
    const float* __restrict__ bias, const float* __restrict__ W4,
    const float* __restrict__ b4, float* __restrict__ out) {
    extern __shared__ __align__(16) char dyn[];
    const uint32_t sbase = smem_u32(dyn);
    const uint32_t* smem_u = reinterpret_cast<const uint32_t*>(dyn);
    float* sred = reinterpret_cast<float*>(dyn + G64_DYN_SMEM);  // [64][2]

    const int K = HIDDEN / 2;   // 256
    const int tid = threadIdx.x;
    const int wid = tid >> 5;
    const int lane = tid & 31;
    const int g = lane >> 2, tig = lane & 3;
    const int wm = (wid & 1) * 32;
    const int wn = (wid >> 1) * 64;
    const int wnIdx = wid >> 1;
    const int m0 = blockIdx.x * 64;
    const int Cn = K >> 5;   // 8

    float acc[2][8][4];
#pragma unroll
    for (int i = 0; i < 2; i++)
#pragma unroll
        for (int j = 0; j < 8; j++)
#pragma unroll
            for (int q = 0; q < 4; q++) acc[i][j][q] = 0.0f;

    g64_stage(A, Bt, K, m0, 0, 0, sbase, tid);

    for (int c = 0; c < Cn; c++) {
        if (c + 1 < Cn) {
            g64_stage(A, Bt, K, m0, 0, (c + 1) * 32,
                      sbase + ((c + 1) & 1) * G64_STAGE_BYTES, tid);
            asm volatile("cp.async.wait_group 1;" ::: "memory");
        } else {
            asm volatile("cp.async.wait_group 0;" ::: "memory");
        }
        __syncthreads();

        const uint32_t* As = smem_u + (c & 1) * G64_STAGE_FLOATS;
        const uint32_t* Bs = As + 64 * ROWSTRIDE;

#pragma unroll
        for (int kk = 0; kk < 4; kk++) {
            const int kb = kk * 8;
            uint32_t a[2][4];
#pragma unroll
            for (int i = 0; i < 2; i++) {
                const int m = wm + i * 16 + g;
                a[i][0] = As[m * ROWSTRIDE + kb + tig];
                a[i][1] = As[(m + 8) * ROWSTRIDE + kb + tig];
                a[i][2] = As[m * ROWSTRIDE + kb + tig + 4];
                a[i][3] = As[(m + 8) * ROWSTRIDE + kb + tig + 4];
            }
#pragma unroll
            for (int j = 0; j < 8; j++) {
                const int n = wn + j * 8 + g;
                uint32_t b0 = Bs[n * ROWSTRIDE + kb + tig];
                uint32_t b1 = Bs[n * ROWSTRIDE + kb + tig + 4];
                mma_tf32(acc[0][j], a[0], b0, b1);
                mma_tf32(acc[1][j], a[1], b0, b1);
            }
        }
        __syncthreads();
    }

    // Fused reduction epilogue: partial dot with W4 over this warp's 64 cols
    float part[2][2] = {{0.0f, 0.0f}, {0.0f, 0.0f}};
#pragma unroll
    for (int i = 0; i < 2; i++) {
#pragma unroll
        for (int j = 0; j < 8; j++) {
            const int col = wn + j * 8 + tig * 2;
            float w0 = W4[col], w1 = W4[col + 1];
            float bc0 = bias[col], bc1 = bias[col + 1];
            part[i][0] += tanhf(acc[i][j][0] + bc0) * w0 + tanhf(acc[i][j][1] + bc1) * w1;
            part[i][1] += tanhf(acc[i][j][2] + bc0) * w0 + tanhf(acc[i][j][3] + bc1) * w1;
        }
    }
#pragma unroll
    for (int i = 0; i < 2; i++)
#pragma unroll
        for (int h = 0; h < 2; h++) {
            part[i][h] += __shfl_xor_sync(0xFFFFFFFFu, part[i][h], 1);
            part[i][h] += __shfl_xor_sync(0xFFFFFFFFu, part[i][h], 2);
        }
    if (tig == 0) {
#pragma unroll
        for (int i = 0; i < 2; i++)
#pragma unroll
            for (int h = 0; h < 2; h++)
                sred[(wm + i * 16 + g + h * 8) * 2 + wnIdx] = part[i][h];
    }
    __syncthreads();
    if (tid < 64) {
        float s = sred[tid * 2] + sred[tid * 2 + 1] + b4[0];
        out[m0 + tid] = sigmoidf_(s);
    }
}

// ---------------------------------------------------------------------------
// Launch
// ---------------------------------------------------------------------------
extern "C" void kernel_launch(void* const* d_in, const int* in_sizes, int n_in,
                              void* d_out, int out_size) {
    const float* z       = (const float*)d_in[0];
    const int*   sid     = (const int*)d_in[1];
    const int*   eid     = (const int*)d_in[2];
    const float* kp      = (const float*)d_in[3];
    const float* w_stat  = (const float*)d_in[4];
    const float* b_stat  = (const float*)d_in[5];
    const float* w_kdiff = (const float*)d_in[6];
    const float* b_kdiff = (const float*)d_in[7];
    const float* W1      = (const float*)d_in[8];
    const float* b1      = (const float*)d_in[9];
    const float* W2      = (const float*)d_in[10];
    const float* b2      = (const float*)d_in[11];
    const float* W3      = (const float*)d_in[12];
    const float* b3      = (const float*)d_in[13];
    const float* W4      = (const float*)d_in[14];
    const float* b4      = (const float*)d_in[15];
    float* out = (float*)d_out;

    float *pState, *pH1, *pH2, *pKnowS, *pKnowK, *pW1t, *pW2t, *pW3t;
    cudaGetSymbolAddress((void**)&pState, g_state);
    cudaGetSymbolAddress((void**)&pH1, g_h1);
    cudaGetSymbolAddress((void**)&pH2, g_h2);
    cudaGetSymbolAddress((void**)&pKnowS, g_knowS);
    cudaGetSymbolAddress((void**)&pKnowK, g_knowK);
    cudaGetSymbolAddress((void**)&pW1t, g_W1t);
    cudaGetSymbolAddress((void**)&pW2t, g_W2t);
    cudaGetSymbolAddress((void**)&pW3t, g_W3t);

    const float* know = z + (size_t)(STU_NUM + PROB_NUM) * DIM;

    static bool attr_set = false;
    if (!attr_set) {
        cudaFuncSetAttribute(fused1_kernel, cudaFuncAttributeMaxDynamicSharedMemorySize, F1_DYN_SMEM);
        cudaFuncSetAttribute(mma_gemm64, cudaFuncAttributeMaxDynamicSharedMemorySize, G64_DYN_SMEM);
        cudaFuncSetAttribute(gemm3_final_kernel, cudaFuncAttributeMaxDynamicSharedMemorySize, GD_DYN_SMEM);
        attr_set = true;
    }

    // 1. prep
    prep_kernel<<<dim3(16, 16, 4), dim3(32, 8)>>>(W1, W2, W3, know, w_stat, w_kdiff,
                                                  pW1t, pW2t, pW3t, pKnowS, pKnowK);

    // 2. fused gather + dual GEMM + combine -> state
    fused1_kernel<<<BATCH / 64, 256, F1_DYN_SMEM>>>(z, sid, eid, pKnowS, pKnowK,
                                                    kp, b_stat, b_kdiff, pState);

    // 3. h1 = round(tanh(state @ W1 + b1))   (8192 x 512 x 128) — 512 CTAs
    mma_gemm64<<<dim3(4, 128), 128, G64_DYN_SMEM>>>(pState, pW1t, b1, pH1,
                                                    BATCH, HIDDEN, KNOW_NUM);

    // 4. h2 = round(tanh(h1 @ W2 + b2))      (8192 x 256 x 512) — 256 CTAs
    mma_gemm64<<<dim3(2, 128), 128, G64_DYN_SMEM>>>(pH1, pW2t, b2, pH2,
                                                    BATCH, HIDDEN / 2, HIDDEN);

    // 5. fused h3 GEMM + final dot + sigmoid — 128 CTAs
    gemm3_final_kernel<<<BATCH / 64, 128, GD_DYN_SMEM>>>(pH2, pW3t, b3, W4, b4, out);
}